// round 1
// baseline (speedup 1.0000x reference)
#include <cuda_runtime.h>
#include <cuda_bf16.h>

// Dynamic per-pixel depthwise 3x3 conv, stride 1, pad 1.
// input : [B=8, C=64, H=128, W=128]           float32
// weight: [B, C, 3, 3, outH=128, outW=128]    float32
// out   : [B, C, 128, 128]                    float32
//
// Each thread computes 4 consecutive ow pixels so that every weight tap is a
// coalesced float4 load (weights for a tap are contiguous over (oh,ow)).

#define B_  8
#define C_  64
#define H_  128
#define W_  128
#define HW_ (H_ * W_)
#define CHW_ (C_ * HW_)

__global__ __launch_bounds__(256)
void dydconv_kernel(const float* __restrict__ input,
                    const float* __restrict__ weight,
                    float* __restrict__ out)
{
    // one thread = 4 pixels along ow
    const int tid = blockIdx.x * blockDim.x + threadIdx.x;
    const int quads_per_row = W_ / 4;                 // 32
    const int ow4 = (tid & (quads_per_row - 1)) * 4;  // 0,4,...,124
    int t = tid >> 5;                                 // / quads_per_row
    const int oh = t & (H_ - 1);
    t >>= 7;                                          // / H_
    const int c = t & (C_ - 1);
    const int b = t >> 6;                             // / C_
    if (b >= B_) return;

    const int bc = b * C_ + c;
    // weight layout: (((bc*3 + kh)*3 + kw)*H_ + oh)*W_ + ow
    const long wbase = ((long)bc * 9) * (long)HW_ + (long)oh * W_ + ow4;
    const int ibase_bc = bc * HW_;

    float4 acc = make_float4(0.f, 0.f, 0.f, 0.f);

    #pragma unroll
    for (int kh = 0; kh < 3; ++kh) {
        const int ih = oh + kh - 1;
        float in_row[6];
        if (ih >= 0 && ih < H_) {
            const float* __restrict__ irow = input + ibase_bc + ih * W_;
            #pragma unroll
            for (int tt = 0; tt < 6; ++tt) {
                const int iw = ow4 - 1 + tt;
                in_row[tt] = (iw >= 0 && iw < W_) ? __ldg(irow + iw) : 0.f;
            }
        } else {
            #pragma unroll
            for (int tt = 0; tt < 6; ++tt) in_row[tt] = 0.f;
        }

        #pragma unroll
        for (int kw = 0; kw < 3; ++kw) {
            const float4 w = *reinterpret_cast<const float4*>(
                weight + wbase + (long)(kh * 3 + kw) * HW_);
            acc.x = fmaf(w.x, in_row[kw + 0], acc.x);
            acc.y = fmaf(w.y, in_row[kw + 1], acc.y);
            acc.z = fmaf(w.z, in_row[kw + 2], acc.z);
            acc.w = fmaf(w.w, in_row[kw + 3], acc.w);
        }
    }

    *reinterpret_cast<float4*>(out + ibase_bc + oh * W_ + ow4) = acc;
}

extern "C" void kernel_launch(void* const* d_in, const int* in_sizes, int n_in,
                              void* d_out, int out_size)
{
    const float* input  = (const float*)d_in[0];
    const float* weight = (const float*)d_in[1];
    float* out = (float*)d_out;

    const int total_quads = B_ * C_ * H_ * (W_ / 4);  // 2,097,152
    const int threads = 256;
    const int blocks = total_quads / threads;         // 8192
    dydconv_kernel<<<blocks, threads>>>(input, weight, out);
}

// round 2
// speedup vs baseline: 1.1245x; 1.1245x over previous
#include <cuda_runtime.h>
#include <cuda_bf16.h>

// Dynamic per-pixel depthwise 3x3 conv, stride 1, pad 1.
// input : [B=8, C=64, H=128, W=128]           float32
// weight: [B, C, 3, 3, outH=128, outW=128]    float32
// out   : [B, C, 128, 128]                    float32
//
// HBM-bound (369 MB min traffic, weights dominate at 302 MB read-once).
// Each thread computes 8 consecutive ow pixels:
//  - every weight tap: two aligned float4 streaming loads (__ldcs, no reuse)
//  - input row: two aligned float4 loads + 2 predicated halo scalars
//  - output: two STG.128
// Goal: maximize per-warp MLP to push achieved HBM BW toward ceiling.

#define B_  8
#define C_  64
#define H_  128
#define W_  128
#define HW_ (H_ * W_)

__global__ __launch_bounds__(256)
void dydconv_kernel(const float* __restrict__ input,
                    const float* __restrict__ weight,
                    float* __restrict__ out)
{
    // one thread = 8 pixels along ow
    const int tid = blockIdx.x * blockDim.x + threadIdx.x;
    const int oct_per_row = W_ / 8;                   // 16
    const int ow8 = (tid & (oct_per_row - 1)) * 8;    // 0,8,...,120
    int t = tid >> 4;                                 // / oct_per_row
    const int oh = t & (H_ - 1);
    t >>= 7;                                          // / H_
    const int bc = t;                                 // 0..511

    // weight layout: (((bc*3 + kh)*3 + kw)*H_ + oh)*W_ + ow
    const long wbase = ((long)bc * 9) * (long)HW_ + (long)oh * W_ + ow8;
    const int ibase = bc * HW_ + oh * W_ + ow8;

    // input rows: ih = oh-1, oh, oh+1 ; each row needs [ow8-1 .. ow8+8] = 10 floats
    float in_rows[3][10];
    #pragma unroll
    for (int kh = 0; kh < 3; ++kh) {
        const int ih = oh + kh - 1;
        if (ih >= 0 && ih < H_) {
            const float* __restrict__ irow = input + bc * HW_ + ih * W_ + ow8;
            const float4 a = __ldg(reinterpret_cast<const float4*>(irow));
            const float4 bq = __ldg(reinterpret_cast<const float4*>(irow + 4));
            in_rows[kh][0] = (ow8 > 0)        ? __ldg(irow - 1) : 0.f;
            in_rows[kh][9] = (ow8 + 8 < W_)   ? __ldg(irow + 8) : 0.f;
            in_rows[kh][1] = a.x;  in_rows[kh][2] = a.y;
            in_rows[kh][3] = a.z;  in_rows[kh][4] = a.w;
            in_rows[kh][5] = bq.x; in_rows[kh][6] = bq.y;
            in_rows[kh][7] = bq.z; in_rows[kh][8] = bq.w;
        } else {
            #pragma unroll
            for (int tt = 0; tt < 10; ++tt) in_rows[kh][tt] = 0.f;
        }
    }

    float4 acc0 = make_float4(0.f, 0.f, 0.f, 0.f);
    float4 acc1 = make_float4(0.f, 0.f, 0.f, 0.f);

    #pragma unroll
    for (int kh = 0; kh < 3; ++kh) {
        #pragma unroll
        for (int kw = 0; kw < 3; ++kw) {
            const float* wp = weight + wbase + (long)(kh * 3 + kw) * HW_;
            const float4 w0 = __ldcs(reinterpret_cast<const float4*>(wp));
            const float4 w1 = __ldcs(reinterpret_cast<const float4*>(wp + 4));
            const float* r = in_rows[kh];
            acc0.x = fmaf(w0.x, r[kw + 0], acc0.x);
            acc0.y = fmaf(w0.y, r[kw + 1], acc0.y);
            acc0.z = fmaf(w0.z, r[kw + 2], acc0.z);
            acc0.w = fmaf(w0.w, r[kw + 3], acc0.w);
            acc1.x = fmaf(w1.x, r[kw + 4], acc1.x);
            acc1.y = fmaf(w1.y, r[kw + 5], acc1.y);
            acc1.z = fmaf(w1.z, r[kw + 6], acc1.z);
            acc1.w = fmaf(w1.w, r[kw + 7], acc1.w);
        }
    }

    *reinterpret_cast<float4*>(out + ibase)     = acc0;
    *reinterpret_cast<float4*>(out + ibase + 4) = acc1;
}

extern "C" void kernel_launch(void* const* d_in, const int* in_sizes, int n_in,
                              void* d_out, int out_size)
{
    const float* input  = (const float*)d_in[0];
    const float* weight = (const float*)d_in[1];
    float* out = (float*)d_out;

    const int total_octs = B_ * C_ * H_ * (W_ / 8);   // 1,048,576
    const int threads = 256;
    const int blocks = total_octs / threads;          // 4096
    dydconv_kernel<<<blocks, threads>>>(input, weight, out);
}